// round 13
// baseline (speedup 1.0000x reference)
#include <cuda_runtime.h>
#include <cuda_bf16.h>
#include <mma.h>
#include <math.h>
#include <stddef.h>

using namespace nvcuda;

#define S 4096
#define H 256
#define NH 6
#define G3 768
#define EPS 1e-5f

// ---------------- scratch (static device arrays; no allocation) ----------------
__device__ float g_x[S * H];            // embedded tokens
__device__ float g_q[NH * S * H];
__device__ float g_k[NH * S * H];
__device__ float g_v[NH * S * H];
__device__ float g_o[NH * S * H];       // attention output per head
__device__ float g_ypre[S * H];         // x + attn_proj (pre-LN)
__device__ float g_y[S * H];            // post-LN
__device__ float g_gi[S * G3];          // y @ W_ih^T + b_ih

// ---------------- embedding gather ----------------
__global__ void embed_kernel(const int* __restrict__ tokens,
                             const float* __restrict__ emb) {
    int s = blockIdx.x;
    int tok = tokens[s];
    const float4* src = (const float4*)(emb + (size_t)tok * H);
    float4* dst = (float4*)(g_x + (size_t)s * H);
    dst[threadIdx.x] = src[threadIdx.x];   // 64 threads * 4
}

// ---------------- WMMA tf32 QKV GEMM, all 3 projections in one launch --------
// z = 0..17: which = z/6 (0=Q,1=K,2=V), head = z%6
#define LDG_ 68
__global__ __launch_bounds__(256) void gemm_qkv(const float* __restrict__ A,
                                                const float* __restrict__ Wq,
                                                const float* __restrict__ bq,
                                                const float* __restrict__ Wk,
                                                const float* __restrict__ bk,
                                                const float* __restrict__ Wv,
                                                const float* __restrict__ bv,
                                                float* __restrict__ Cq,
                                                float* __restrict__ Ck,
                                                float* __restrict__ Cv) {
    __shared__ float As[64 * LDG_];
    __shared__ float Bs[64 * LDG_];
    int tid = threadIdx.x;
    int warp = tid >> 5;
    int wm = warp & 3;
    int wn = warp >> 2;
    int m0 = blockIdx.y * 64, n0 = blockIdx.x * 64;
    int z = blockIdx.z;
    int which = z / 6, zh = z - which * 6;
    const float* Bb = ((which == 0) ? Wq : (which == 1) ? Wk : Wv) +
                      (size_t)zh * 256 * 256;
    const float* bias = ((which == 0) ? bq : (which == 1) ? bk : bv) + zh * 256;
    float* C = ((which == 0) ? Cq : (which == 1) ? Ck : Cv);

    wmma::fragment<wmma::accumulator, 16, 16, 8, float> c[2];
    wmma::fill_fragment(c[0], 0.0f);
    wmma::fill_fragment(c[1], 0.0f);

    for (int k0 = 0; k0 < 256; k0 += 64) {
        const float* Asrc = A + k0;
        for (int i = tid; i < 64 * 16; i += 256) {
            int m = i >> 4, k4 = i & 15;
            float4 v = *(const float4*)(Asrc + (size_t)(m0 + m) * 256 + k4 * 4);
            *(float4*)(As + m * LDG_ + k4 * 4) = v;
        }
        for (int i = tid; i < 64 * 16; i += 256) {
            int kk = i >> 4, n4 = i & 15;
            float4 v = *(const float4*)(Bb + (size_t)(k0 + kk) * 256 + n0 + n4 * 4);
            *(float4*)(Bs + kk * LDG_ + n4 * 4) = v;
        }
        __syncthreads();

        wmma::fragment<wmma::matrix_a, 16, 16, 8, wmma::precision::tf32,
                       wmma::row_major> af;
        wmma::fragment<wmma::matrix_b, 16, 16, 8, wmma::precision::tf32,
                       wmma::row_major> bf;
#pragma unroll
        for (int k = 0; k < 8; k++) {
            wmma::load_matrix_sync(af, As + (wm * 16) * LDG_ + k * 8, LDG_);
#pragma unroll
            for (int e = 0; e < af.num_elements; e++)
                af.x[e] = wmma::__float_to_tf32(af.x[e]);
#pragma unroll
            for (int nf = 0; nf < 2; nf++) {
                wmma::load_matrix_sync(
                    bf, Bs + (k * 8) * LDG_ + wn * 32 + nf * 16, LDG_);
#pragma unroll
                for (int e = 0; e < bf.num_elements; e++)
                    bf.x[e] = wmma::__float_to_tf32(bf.x[e]);
                wmma::mma_sync(c[nf], af, bf, c[nf]);
            }
        }
        __syncthreads();
    }

#pragma unroll
    for (int nf = 0; nf < 2; nf++)
        wmma::store_matrix_sync(As + (wm * 16) * LDG_ + wn * 32 + nf * 16,
                                c[nf], LDG_, wmma::mem_row_major);
    __syncthreads();

    for (int i = tid; i < 64 * 64; i += 256) {
        int m = i >> 6, n = i & 63;
        int gm = m0 + m, gn = n0 + n;
        float v = As[m * LDG_ + n] + bias[gn];
        C[(size_t)zh * S * 256 + (size_t)gm * 256 + gn] = v;
    }
}

// ---------------- WMMA tf32 out-proj (+residual) -----------------------------
__global__ __launch_bounds__(256) void gemm_op(const float* __restrict__ A,
                                               const float* __restrict__ B,
                                               const float* __restrict__ bias,
                                               const float* __restrict__ resid,
                                               float* __restrict__ C) {
    __shared__ float As[64 * LDG_];
    __shared__ float Bs[64 * LDG_];
    int tid = threadIdx.x;
    int warp = tid >> 5;
    int wm = warp & 3;
    int wn = warp >> 2;
    int m0 = blockIdx.y * 64, n0 = blockIdx.x * 64;

    wmma::fragment<wmma::accumulator, 16, 16, 8, float> c[2];
    wmma::fill_fragment(c[0], 0.0f);
    wmma::fill_fragment(c[1], 0.0f);

    for (int k0 = 0; k0 < 1536; k0 += 64) {
        const float* Asrc = A + (size_t)(k0 >> 8) * (S * 256) + (k0 & 255);
        for (int i = tid; i < 64 * 16; i += 256) {
            int m = i >> 4, k4 = i & 15;
            float4 v = *(const float4*)(Asrc + (size_t)(m0 + m) * 256 + k4 * 4);
            *(float4*)(As + m * LDG_ + k4 * 4) = v;
        }
        for (int i = tid; i < 64 * 16; i += 256) {
            int kk = i >> 4, n4 = i & 15;
            float4 v = *(const float4*)(B + (size_t)(k0 + kk) * 256 + n0 + n4 * 4);
            *(float4*)(Bs + kk * LDG_ + n4 * 4) = v;
        }
        __syncthreads();

        wmma::fragment<wmma::matrix_a, 16, 16, 8, wmma::precision::tf32,
                       wmma::row_major> af;
        wmma::fragment<wmma::matrix_b, 16, 16, 8, wmma::precision::tf32,
                       wmma::row_major> bf;
#pragma unroll
        for (int k = 0; k < 8; k++) {
            wmma::load_matrix_sync(af, As + (wm * 16) * LDG_ + k * 8, LDG_);
#pragma unroll
            for (int e = 0; e < af.num_elements; e++)
                af.x[e] = wmma::__float_to_tf32(af.x[e]);
#pragma unroll
            for (int nf = 0; nf < 2; nf++) {
                wmma::load_matrix_sync(
                    bf, Bs + (k * 8) * LDG_ + wn * 32 + nf * 16, LDG_);
#pragma unroll
                for (int e = 0; e < bf.num_elements; e++)
                    bf.x[e] = wmma::__float_to_tf32(bf.x[e]);
                wmma::mma_sync(c[nf], af, bf, c[nf]);
            }
        }
        __syncthreads();
    }

#pragma unroll
    for (int nf = 0; nf < 2; nf++)
        wmma::store_matrix_sync(As + (wm * 16) * LDG_ + wn * 32 + nf * 16,
                                c[nf], LDG_, wmma::mem_row_major);
    __syncthreads();

    for (int i = tid; i < 64 * 64; i += 256) {
        int m = i >> 6, n = i & 63;
        int gm = m0 + m, gn = n0 + n;
        float v = As[m * LDG_ + n] + bias[gn] + resid[(size_t)gm * 256 + gn];
        C[(size_t)gm * 256 + gn] = v;
    }
}

// ---------------- fp32 SIMT GEMM for gi = y @ W_ih^T + b_ih ------------------
__global__ __launch_bounds__(256) void gemm_gi(const float* __restrict__ A,
                                               const float* __restrict__ B,
                                               const float* __restrict__ bias,
                                               float* __restrict__ C) {
    __shared__ float As[64][65];
    __shared__ float Bs[64][65];
    int tid = threadIdx.x;
    int m0 = blockIdx.y * 64, n0 = blockIdx.x * 64;

    float acc[4][4];
#pragma unroll
    for (int i = 0; i < 4; i++)
#pragma unroll
        for (int j = 0; j < 4; j++) acc[i][j] = 0.f;

    int ty = tid >> 4, tx = tid & 15;

    for (int k0 = 0; k0 < 256; k0 += 64) {
#pragma unroll
        for (int i = 0; i < 16; i++) {
            int lin = i * 256 + tid;
            int m = lin >> 6, kk = lin & 63;
            As[m][kk] = A[(size_t)(m0 + m) * 256 + k0 + kk];
        }
#pragma unroll
        for (int i = 0; i < 16; i++) {
            int lin = i * 256 + tid;
            int n = lin >> 6, kk = lin & 63;
            Bs[kk][n] = B[(size_t)(n0 + n) * 256 + (k0 + kk)];
        }
        __syncthreads();
#pragma unroll 8
        for (int kk = 0; kk < 64; kk++) {
            float a[4], b[4];
#pragma unroll
            for (int i = 0; i < 4; i++) a[i] = As[ty * 4 + i][kk];
#pragma unroll
            for (int j = 0; j < 4; j++) b[j] = Bs[kk][tx * 4 + j];
#pragma unroll
            for (int i = 0; i < 4; i++)
#pragma unroll
                for (int j = 0; j < 4; j++) acc[i][j] += a[i] * b[j];
        }
        __syncthreads();
    }

#pragma unroll
    for (int i = 0; i < 4; i++) {
        int m = m0 + ty * 4 + i;
#pragma unroll
        for (int j = 0; j < 4; j++) {
            int n = n0 + tx * 4 + j;
            C[(size_t)m * 768 + n] = acc[i][j] + bias[n];
        }
    }
}

// ---------------- WMMA tf32 streaming attention ------------------------------
#define LDQ 268
#define LDP 76
__global__ __launch_bounds__(256) void attn_kernel(const float* __restrict__ Q,
                                                   const float* __restrict__ K,
                                                   const float* __restrict__ V,
                                                   float* __restrict__ O) {
    extern __shared__ float sm[];
    float* Qs = sm;
    float* Ks = Qs + 64 * LDQ;
    float* Vs = Ks + 64 * LDQ;
    float* Ps = Vs + 64 * LDQ;
    float* Ls = Ps + 64 * LDP;

    int h = blockIdx.y;
    int q0 = blockIdx.x * 64;
    int tid = threadIdx.x;
    int warp = tid >> 5;
    int wm = warp & 3;
    int wn = warp >> 2;

    const float* Qg = Q + ((size_t)h * S + q0) * H;
    const float* Kg = K + (size_t)h * S * H;
    const float* Vg = V + (size_t)h * S * H;

    for (int i = tid; i < 64 * 64; i += 256) {
        int q = i >> 6, d4 = i & 63;
        ((float4*)(Qs + q * LDQ))[d4] = ((const float4*)(Qg + (size_t)q * H))[d4];
    }

    wmma::fragment<wmma::accumulator, 16, 16, 8, float> o_frag[8];
#pragma unroll
    for (int f = 0; f < 8; f++) wmma::fill_fragment(o_frag[f], 0.0f);

    int lrow = tid >> 2;
    int lcol0 = (tid & 3) * 16;
    float l_part = 0.f;
    const float inv_scale = 0.0625f;

    for (int kt = 0; kt < S / 64; kt++) {
        __syncthreads();
        for (int i = tid; i < 64 * 64; i += 256) {
            int r = i >> 6, d4 = i & 63;
            ((float4*)(Ks + r * LDQ))[d4] =
                ((const float4*)(Kg + (size_t)(kt * 64 + r) * H))[d4];
            ((float4*)(Vs + r * LDQ))[d4] =
                ((const float4*)(Vg + (size_t)(kt * 64 + r) * H))[d4];
        }
        __syncthreads();

        {
            wmma::fragment<wmma::matrix_a, 16, 16, 8, wmma::precision::tf32,
                           wmma::row_major> af;
            wmma::fragment<wmma::matrix_b, 16, 16, 8, wmma::precision::tf32,
                           wmma::col_major> bf;
            wmma::fragment<wmma::accumulator, 16, 16, 8, float> c[2];
            wmma::fill_fragment(c[0], 0.0f);
            wmma::fill_fragment(c[1], 0.0f);
#pragma unroll 4
            for (int k = 0; k < 32; k++) {
                wmma::load_matrix_sync(af, Qs + (wm * 16) * LDQ + k * 8, LDQ);
#pragma unroll
                for (int e = 0; e < af.num_elements; e++)
                    af.x[e] = wmma::__float_to_tf32(af.x[e]);
#pragma unroll
                for (int nf = 0; nf < 2; nf++) {
                    wmma::load_matrix_sync(
                        bf, Ks + (wn * 32 + nf * 16) * LDQ + k * 8, LDQ);
#pragma unroll
                    for (int e = 0; e < bf.num_elements; e++)
                        bf.x[e] = wmma::__float_to_tf32(bf.x[e]);
                    wmma::mma_sync(c[nf], af, bf, c[nf]);
                }
            }
#pragma unroll
            for (int nf = 0; nf < 2; nf++)
                wmma::store_matrix_sync(
                    Ps + (wm * 16) * LDP + wn * 32 + nf * 16, c[nf], LDP,
                    wmma::mem_row_major);
        }
        __syncthreads();

        {
            float* pr = Ps + lrow * LDP + lcol0;
            float ssum = 0.f;
#pragma unroll
            for (int j = 0; j < 16; j++) {
                float e = __expf(pr[j] * inv_scale);
                pr[j] = e;
                ssum += e;
            }
            l_part += ssum;
        }
        __syncthreads();

        {
            wmma::fragment<wmma::matrix_a, 16, 16, 8, wmma::precision::tf32,
                           wmma::row_major> pa;
            wmma::fragment<wmma::matrix_b, 16, 16, 8, wmma::precision::tf32,
                           wmma::row_major> vb;
#pragma unroll
            for (int k = 0; k < 8; k++) {
                wmma::load_matrix_sync(pa, Ps + (wm * 16) * LDP + k * 8, LDP);
#pragma unroll
                for (int e = 0; e < pa.num_elements; e++)
                    pa.x[e] = wmma::__float_to_tf32(pa.x[e]);
#pragma unroll
                for (int nf = 0; nf < 8; nf++) {
                    wmma::load_matrix_sync(
                        vb, Vs + (k * 8) * LDQ + wn * 128 + nf * 16, LDQ);
#pragma unroll
                    for (int e = 0; e < vb.num_elements; e++)
                        vb.x[e] = wmma::__float_to_tf32(vb.x[e]);
                    wmma::mma_sync(o_frag[nf], pa, vb, o_frag[nf]);
                }
            }
        }
    }

    l_part += __shfl_xor_sync(0xffffffffu, l_part, 1);
    l_part += __shfl_xor_sync(0xffffffffu, l_part, 2);
    if ((tid & 3) == 0) Ls[lrow] = l_part;

#pragma unroll
    for (int nf = 0; nf < 8; nf++)
        wmma::store_matrix_sync(Qs + (wm * 16) * LDQ + wn * 128 + nf * 16,
                                o_frag[nf], LDQ, wmma::mem_row_major);
    __syncthreads();

    float* Og = O + ((size_t)h * S + q0) * H;
    for (int i = tid; i < 64 * 64; i += 256) {
        int q = i >> 6, d4 = i & 63;
        float inv_l = __frcp_rn(Ls[q]);
        float4 v = ((float4*)(Qs + q * LDQ))[d4];
        v.x *= inv_l; v.y *= inv_l; v.z *= inv_l; v.w *= inv_l;
        ((float4*)(Og + (size_t)q * H))[d4] = v;
    }
}

// ---------------- LayerNorm (one warp per row) ----------------
__global__ __launch_bounds__(256) void ln_kernel(const float* __restrict__ yin,
                                                 const float* __restrict__ g,
                                                 const float* __restrict__ b,
                                                 float* __restrict__ yout) {
    int row = blockIdx.x * 8 + (threadIdx.x >> 5);
    int lane = threadIdx.x & 31;
    const float* yr = yin + (size_t)row * H;
    float v[8], s = 0.f, sq = 0.f;
#pragma unroll
    for (int i = 0; i < 8; i++) {
        v[i] = yr[lane + i * 32];
        s += v[i];
        sq += v[i] * v[i];
    }
#pragma unroll
    for (int m = 16; m >= 1; m >>= 1) {
        s += __shfl_xor_sync(0xffffffffu, s, m);
        sq += __shfl_xor_sync(0xffffffffu, sq, m);
    }
    float mu = s * (1.f / H);
    float var = sq * (1.f / H) - mu * mu;
    float rstd = rsqrtf(var + EPS);
    float* yo = yout + (size_t)row * H;
#pragma unroll
    for (int i = 0; i < 8; i++) {
        int c = lane + i * 32;
        yo[c] = (v[i] - mu) * rstd * g[c] + b[c];
    }
}

// ---------------- GRU recurrence: 8-CTA cluster, 4-way-spread st.async -------
// R13: tx traffic spread across 4 mbarriers per parity (warp w -> group w&3),
// so the per-address mbar update serialization (~13 cyc/msg, 128 msgs) becomes
// 4 parallel streams of 32. Waits run in parallel on lanes 0..3, merged by
// __syncwarp (same elected-acquire pattern as R10/R11). Re-arm by tids 0..3.
#define RB 8
#define RT 512

__device__ __forceinline__ unsigned int smem_u32(const void* p) {
    unsigned int a;
    asm("{ .reg .u64 t; cvta.to.shared.u64 t, %1; cvt.u32.u64 %0, t; }"
        : "=r"(a) : "l"(p));
    return a;
}

__device__ __forceinline__ void cluster_arrive_wait() {
    asm volatile("barrier.cluster.arrive.aligned;" ::: "memory");
    asm volatile("barrier.cluster.wait.aligned;" ::: "memory");
}

__device__ __forceinline__ void mbar_wait_parity(unsigned int mb,
                                                 unsigned int parity) {
    asm volatile(
        "{\n\t"
        ".reg .pred P;\n\t"
        "WL%=:\n\t"
        "mbarrier.try_wait.parity.acquire.cta.shared::cta.b64 P, [%0], %1, 0x989680;\n\t"
        "@!P bra WL%=;\n\t"
        "}"
        :: "r"(mb), "r"(parity) : "memory");
}

__global__ void __cluster_dims__(RB, 1, 1) __launch_bounds__(RT, 1)
rnn_kernel(const float* __restrict__ gi,
           const float* __restrict__ Whh,
           const float* __restrict__ bhh,
           float* __restrict__ out,
           int out_size) {
    __shared__ __align__(16) float hbuf[2][H];
    __shared__ __align__(8) unsigned long long mbar[2][4];  // [parity][group]

    int blk = blockIdx.x;
    int tid = threadIdx.x;
    int w = tid >> 5;                 // warp 0..15
    int lane = tid & 31;
    int grp = w & 3;                  // this warp's mbar group

    unsigned long long w2[6][4];
#pragma unroll
    for (int g = 0; g < 3; g++) {
#pragma unroll
        for (int dd = 0; dd < 2; dd++) {
            int rowg = g * 256 + blk * 32 + w * 2 + dd;
            const unsigned long long* src =
                (const unsigned long long*)(Whh + (size_t)rowg * H + lane * 8);
#pragma unroll
            for (int i = 0; i < 4; i++) w2[g * 2 + dd][i] = src[i];
        }
    }

    for (int i = tid; i < 2 * H; i += RT) ((float*)hbuf)[i] = 0.f;

    // local mbar addresses (parity-major)
    unsigned int lm[2][4];
#pragma unroll
    for (int pp = 0; pp < 2; pp++)
#pragma unroll
        for (int gg = 0; gg < 4; gg++)
            lm[pp][gg] = smem_u32(&mbar[pp][gg]);

    if (tid < 4) {
#pragma unroll
        for (int pp = 0; pp < 2; pp++) {
            asm volatile("mbarrier.init.shared.b64 [%0], %1;"
                         :: "r"(lm[pp][tid]), "r"(1) : "memory");
            asm volatile("mbarrier.arrive.expect_tx.shared.b64 _, [%0], %1;"
                         :: "r"(lm[pp][tid]), "r"(256) : "memory");
        }
    }

    int d = w * 2 + lane;             // local dim, meaningful for lane < 2
    int j = blk * 32 + d;
    int jc = j & 255;
    bool owner = (lane < 2);
    float ir = 0.f, iz = 0.f, inn = 0.f, bh_r = 0.f, bh_z = 0.f, bh_n = 0.f;
    if (owner) {
        ir = gi[j];
        iz = gi[256 + j];
        inn = gi[512 + j];
        bh_r = bhh[j];
        bh_z = bhh[256 + j];
        bh_n = bhh[512 + j];
    }
    unsigned int hb0 = smem_u32(&hbuf[0][lane * 8]);
    unsigned int hb1 = smem_u32(&hbuf[1][lane * 8]);

    // remote addresses for lanes 0..7: data slot + this warp's group mbar
    unsigned int wl0 = smem_u32(&hbuf[0][blk * 32 + w * 2]);
    unsigned int wl1 = smem_u32(&hbuf[1][blk * 32 + w * 2]);
    int rr = lane & 7;
    unsigned int pdst0, pdst1, pmb0, pmb1;
    asm("mapa.shared::cluster.u32 %0, %1, %2;" : "=r"(pdst0) : "r"(wl0), "r"(rr));
    asm("mapa.shared::cluster.u32 %0, %1, %2;" : "=r"(pdst1) : "r"(wl1), "r"(rr));
    asm("mapa.shared::cluster.u32 %0, %1, %2;" : "=r"(pmb0) : "r"(lm[0][grp]), "r"(rr));
    asm("mapa.shared::cluster.u32 %0, %1, %2;" : "=r"(pmb1) : "r"(lm[1][grp]), "r"(rr));

    __syncthreads();
    cluster_arrive_wait();   // hbufs zeroed + mbarriers armed everywhere

    for (int t = 0; t < S; t++) {
        int p = t & 1;

        unsigned int haddr = p ? hb1 : hb0;
        unsigned long long h2[4];
        asm volatile("ld.shared.v2.b64 {%0, %1}, [%4];\n\t"
                     "ld.shared.v2.b64 {%2, %3}, [%4 + 16];"
                     : "=l"(h2[0]), "=l"(h2[1]), "=l"(h2[2]), "=l"(h2[3])
                     : "r"(haddr));
        float a[6];
#pragma unroll
        for (int r = 0; r < 6; r++) {
            unsigned long long acc2 = 0ull;
#pragma unroll
            for (int i = 0; i < 4; i++) {
                asm("fma.rn.f32x2 %0, %1, %2, %0;"
                    : "+l"(acc2) : "l"(w2[r][i]), "l"(h2[i]));
            }
            float lo, hi;
            asm("mov.b64 {%0, %1}, %2;" : "=f"(lo), "=f"(hi) : "l"(acc2));
            a[r] = lo + hi;
        }

        bool odd = (lane & 1);
        float z3[3];
#pragma unroll
        for (int g = 0; g < 3; g++) {
            float x = a[2 * g], y = a[2 * g + 1];
            float keep = odd ? y : x;
            float send = odd ? x : y;
            z3[g] = keep + __shfl_xor_sync(0xffffffffu, send, 1);
        }
#pragma unroll
        for (int m = 2; m <= 16; m <<= 1) {
#pragma unroll
            for (int g = 0; g < 3; g++)
                z3[g] += __shfl_xor_sync(0xffffffffu, z3[g], m);
        }

        float ghr = z3[0] + bh_r;
        float ghz = z3[1] + bh_z;
        float ghn = z3[2] + bh_n;
        float hold = hbuf[p][jc];
        float r = 1.f / (1.f + __expf(-(ir + ghr)));
        float z = 1.f / (1.f + __expf(-(iz + ghz)));
        float narg = inn + r * ghn;
        float n = 1.f - 2.f / (1.f + __expf(2.f * narg));
        float hnew = (1.f - z) * n + z * hold;

        float h0b = __shfl_sync(0xffffffffu, hnew, 0);
        float h1b = __shfl_sync(0xffffffffu, hnew, 1);
        unsigned long long pk;
        asm("mov.b64 %0, {%1, %2};" : "=l"(pk) : "f"(h0b), "f"(h1b));

        if (lane < 8) {
            unsigned int pd = p ? pdst0 : pdst1;   // write hbuf[p^1]
            unsigned int pm = p ? pmb1 : pmb0;     // count on mbar[p][grp]
            asm volatile(
                "st.async.shared::cluster.mbarrier::complete_tx::bytes.b64 "
                "[%0], %1, [%2];"
                :: "r"(pd), "l"(pk), "r"(pm) : "memory");
        }

        if (owner) {
            int tn = (t + 1 < S) ? (t + 1) : t;
            ir = gi[(size_t)tn * G3 + j];
            iz = gi[(size_t)tn * G3 + 256 + j];
            inn = gi[(size_t)tn * G3 + 512 + j];
        }

        // parallel waits: lanes 0..3 each wait one group's mbar of parity p
        unsigned int parity = (unsigned int)((t >> 1) & 1);
        if (lane < 4) {
            mbar_wait_parity(lm[p][lane], parity);
            if (tid < 4) {
                // re-arm this group's mbar for phase t+2 (safe: its phase-t
                // wait just completed; t+2 stores can't exist before all CTAs
                // passed t+1, which transitively requires this re-arm's side)
                asm volatile("mbarrier.arrive.expect_tx.shared.b64 _, [%0], %1;"
                             :: "r"(lm[p][tid]), "r"(256) : "memory");
            }
        }
        __syncwarp();      // carries the acquires to the whole warp
    }

    if (blk == 0) {
        for (int i = tid; i < out_size; i += RT)
            out[i] = hbuf[0][i & 255];
    }
}

// ---------------- host launcher ----------------
extern "C" void kernel_launch(void* const* d_in, const int* in_sizes, int n_in,
                              void* d_out, int out_size) {
    const int* tokens = (const int*)d_in[0];
    const float* emb = (const float*)d_in[1];
    const float* Wq = (const float*)d_in[2];
    const float* bq = (const float*)d_in[3];
    const float* Wk = (const float*)d_in[4];
    const float* bk = (const float*)d_in[5];
    const float* Wv = (const float*)d_in[6];
    const float* bv = (const float*)d_in[7];
    const float* Wo = (const float*)d_in[8];
    const float* bo = (const float*)d_in[9];
    const float* ln_g = (const float*)d_in[10];
    const float* ln_b = (const float*)d_in[11];
    const float* W_ih = (const float*)d_in[12];
    const float* W_hh = (const float*)d_in[13];
    const float* b_ih = (const float*)d_in[14];
    const float* b_hh = (const float*)d_in[15];
    float* out = (float*)d_out;

    float* px; cudaGetSymbolAddress((void**)&px, g_x);
    float* pq; cudaGetSymbolAddress((void**)&pq, g_q);
    float* pk; cudaGetSymbolAddress((void**)&pk, g_k);
    float* pv; cudaGetSymbolAddress((void**)&pv, g_v);
    float* po; cudaGetSymbolAddress((void**)&po, g_o);
    float* pypre; cudaGetSymbolAddress((void**)&pypre, g_ypre);
    float* py; cudaGetSymbolAddress((void**)&py, g_y);
    float* pgi; cudaGetSymbolAddress((void**)&pgi, g_gi);

    size_t attn_smem = (size_t)(3 * 64 * LDQ + 64 * LDP + 64) * sizeof(float);
    cudaFuncSetAttribute(attn_kernel, cudaFuncAttributeMaxDynamicSharedMemorySize,
                         (int)attn_smem);

    embed_kernel<<<S, 64>>>(tokens, emb);

    dim3 gqkv(4, 64, 3 * NH);
    gemm_qkv<<<gqkv, 256>>>(px, Wq, bq, Wk, bk, Wv, bv, pq, pk, pv);

    dim3 gatt(S / 64, NH);
    attn_kernel<<<gatt, 256, attn_smem>>>(pq, pk, pv, po);

    dim3 gop(4, 64, 1);
    gemm_op<<<gop, 256>>>(po, Wo, bo, px, pypre);

    ln_kernel<<<S / 8, 256>>>(pypre, ln_g, ln_b, py);

    dim3 ggi(12, 64, 1);
    gemm_gi<<<ggi, 256>>>(py, W_ih, b_ih, pgi);

    rnn_kernel<<<RB, RT>>>(pgi, W_hh, b_hh, out, out_size);
}

// round 14
// speedup vs baseline: 1.0836x; 1.0836x over previous
#include <cuda_runtime.h>
#include <cuda_bf16.h>
#include <mma.h>
#include <math.h>
#include <stddef.h>

using namespace nvcuda;

#define S 4096
#define H 256
#define NH 6
#define G3 768
#define EPS 1e-5f

// ---------------- scratch (static device arrays; no allocation) ----------------
__device__ float g_x[S * H];
__device__ float g_q[NH * S * H];
__device__ float g_k[NH * S * H];
__device__ float g_v[NH * S * H];
__device__ float g_o[NH * S * H];
__device__ float g_ypre[S * H];
__device__ float g_y[S * H];
__device__ float g_gi[S * G3];

// ---------------- embedding gather ----------------
__global__ void embed_kernel(const int* __restrict__ tokens,
                             const float* __restrict__ emb) {
    int s = blockIdx.x;
    int tok = tokens[s];
    const float4* src = (const float4*)(emb + (size_t)tok * H);
    float4* dst = (float4*)(g_x + (size_t)s * H);
    dst[threadIdx.x] = src[threadIdx.x];
}

// ---------------- WMMA tf32 QKV GEMM, all 3 projections in one launch --------
#define LDG_ 68
__global__ __launch_bounds__(256) void gemm_qkv(const float* __restrict__ A,
                                                const float* __restrict__ Wq,
                                                const float* __restrict__ bq,
                                                const float* __restrict__ Wk,
                                                const float* __restrict__ bk,
                                                const float* __restrict__ Wv,
                                                const float* __restrict__ bv,
                                                float* __restrict__ Cq,
                                                float* __restrict__ Ck,
                                                float* __restrict__ Cv) {
    __shared__ float As[64 * LDG_];
    __shared__ float Bs[64 * LDG_];
    int tid = threadIdx.x;
    int warp = tid >> 5;
    int wm = warp & 3;
    int wn = warp >> 2;
    int m0 = blockIdx.y * 64, n0 = blockIdx.x * 64;
    int z = blockIdx.z;
    int which = z / 6, zh = z - which * 6;
    const float* Bb = ((which == 0) ? Wq : (which == 1) ? Wk : Wv) +
                      (size_t)zh * 256 * 256;
    const float* bias = ((which == 0) ? bq : (which == 1) ? bk : bv) + zh * 256;
    float* C = ((which == 0) ? Cq : (which == 1) ? Ck : Cv);

    wmma::fragment<wmma::accumulator, 16, 16, 8, float> c[2];
    wmma::fill_fragment(c[0], 0.0f);
    wmma::fill_fragment(c[1], 0.0f);

    for (int k0 = 0; k0 < 256; k0 += 64) {
        const float* Asrc = A + k0;
        for (int i = tid; i < 64 * 16; i += 256) {
            int m = i >> 4, k4 = i & 15;
            float4 v = *(const float4*)(Asrc + (size_t)(m0 + m) * 256 + k4 * 4);
            *(float4*)(As + m * LDG_ + k4 * 4) = v;
        }
        for (int i = tid; i < 64 * 16; i += 256) {
            int kk = i >> 4, n4 = i & 15;
            float4 v = *(const float4*)(Bb + (size_t)(k0 + kk) * 256 + n0 + n4 * 4);
            *(float4*)(Bs + kk * LDG_ + n4 * 4) = v;
        }
        __syncthreads();

        wmma::fragment<wmma::matrix_a, 16, 16, 8, wmma::precision::tf32,
                       wmma::row_major> af;
        wmma::fragment<wmma::matrix_b, 16, 16, 8, wmma::precision::tf32,
                       wmma::row_major> bf;
#pragma unroll
        for (int k = 0; k < 8; k++) {
            wmma::load_matrix_sync(af, As + (wm * 16) * LDG_ + k * 8, LDG_);
#pragma unroll
            for (int e = 0; e < af.num_elements; e++)
                af.x[e] = wmma::__float_to_tf32(af.x[e]);
#pragma unroll
            for (int nf = 0; nf < 2; nf++) {
                wmma::load_matrix_sync(
                    bf, Bs + (k * 8) * LDG_ + wn * 32 + nf * 16, LDG_);
#pragma unroll
                for (int e = 0; e < bf.num_elements; e++)
                    bf.x[e] = wmma::__float_to_tf32(bf.x[e]);
                wmma::mma_sync(c[nf], af, bf, c[nf]);
            }
        }
        __syncthreads();
    }

#pragma unroll
    for (int nf = 0; nf < 2; nf++)
        wmma::store_matrix_sync(As + (wm * 16) * LDG_ + wn * 32 + nf * 16,
                                c[nf], LDG_, wmma::mem_row_major);
    __syncthreads();

    for (int i = tid; i < 64 * 64; i += 256) {
        int m = i >> 6, n = i & 63;
        int gm = m0 + m, gn = n0 + n;
        float v = As[m * LDG_ + n] + bias[gn];
        C[(size_t)zh * S * 256 + (size_t)gm * 256 + gn] = v;
    }
}

// ---------------- WMMA tf32 out-proj (+residual) -----------------------------
__global__ __launch_bounds__(256) void gemm_op(const float* __restrict__ A,
                                               const float* __restrict__ B,
                                               const float* __restrict__ bias,
                                               const float* __restrict__ resid,
                                               float* __restrict__ C) {
    __shared__ float As[64 * LDG_];
    __shared__ float Bs[64 * LDG_];
    int tid = threadIdx.x;
    int warp = tid >> 5;
    int wm = warp & 3;
    int wn = warp >> 2;
    int m0 = blockIdx.y * 64, n0 = blockIdx.x * 64;

    wmma::fragment<wmma::accumulator, 16, 16, 8, float> c[2];
    wmma::fill_fragment(c[0], 0.0f);
    wmma::fill_fragment(c[1], 0.0f);

    for (int k0 = 0; k0 < 1536; k0 += 64) {
        const float* Asrc = A + (size_t)(k0 >> 8) * (S * 256) + (k0 & 255);
        for (int i = tid; i < 64 * 16; i += 256) {
            int m = i >> 4, k4 = i & 15;
            float4 v = *(const float4*)(Asrc + (size_t)(m0 + m) * 256 + k4 * 4);
            *(float4*)(As + m * LDG_ + k4 * 4) = v;
        }
        for (int i = tid; i < 64 * 16; i += 256) {
            int kk = i >> 4, n4 = i & 15;
            float4 v = *(const float4*)(B + (size_t)(k0 + kk) * 256 + n0 + n4 * 4);
            *(float4*)(Bs + kk * LDG_ + n4 * 4) = v;
        }
        __syncthreads();

        wmma::fragment<wmma::matrix_a, 16, 16, 8, wmma::precision::tf32,
                       wmma::row_major> af;
        wmma::fragment<wmma::matrix_b, 16, 16, 8, wmma::precision::tf32,
                       wmma::row_major> bf;
#pragma unroll
        for (int k = 0; k < 8; k++) {
            wmma::load_matrix_sync(af, As + (wm * 16) * LDG_ + k * 8, LDG_);
#pragma unroll
            for (int e = 0; e < af.num_elements; e++)
                af.x[e] = wmma::__float_to_tf32(af.x[e]);
#pragma unroll
            for (int nf = 0; nf < 2; nf++) {
                wmma::load_matrix_sync(
                    bf, Bs + (k * 8) * LDG_ + wn * 32 + nf * 16, LDG_);
#pragma unroll
                for (int e = 0; e < bf.num_elements; e++)
                    bf.x[e] = wmma::__float_to_tf32(bf.x[e]);
                wmma::mma_sync(c[nf], af, bf, c[nf]);
            }
        }
        __syncthreads();
    }

#pragma unroll
    for (int nf = 0; nf < 2; nf++)
        wmma::store_matrix_sync(As + (wm * 16) * LDG_ + wn * 32 + nf * 16,
                                c[nf], LDG_, wmma::mem_row_major);
    __syncthreads();

    for (int i = tid; i < 64 * 64; i += 256) {
        int m = i >> 6, n = i & 63;
        int gm = m0 + m, gn = n0 + n;
        float v = As[m * LDG_ + n] + bias[gn] + resid[(size_t)gm * 256 + gn];
        C[(size_t)gm * 256 + gn] = v;
    }
}

// ---------------- fp32 SIMT GEMM for gi = y @ W_ih^T + b_ih ------------------
__global__ __launch_bounds__(256) void gemm_gi(const float* __restrict__ A,
                                               const float* __restrict__ B,
                                               const float* __restrict__ bias,
                                               float* __restrict__ C) {
    __shared__ float As[64][65];
    __shared__ float Bs[64][65];
    int tid = threadIdx.x;
    int m0 = blockIdx.y * 64, n0 = blockIdx.x * 64;

    float acc[4][4];
#pragma unroll
    for (int i = 0; i < 4; i++)
#pragma unroll
        for (int j = 0; j < 4; j++) acc[i][j] = 0.f;

    int ty = tid >> 4, tx = tid & 15;

    for (int k0 = 0; k0 < 256; k0 += 64) {
#pragma unroll
        for (int i = 0; i < 16; i++) {
            int lin = i * 256 + tid;
            int m = lin >> 6, kk = lin & 63;
            As[m][kk] = A[(size_t)(m0 + m) * 256 + k0 + kk];
        }
#pragma unroll
        for (int i = 0; i < 16; i++) {
            int lin = i * 256 + tid;
            int n = lin >> 6, kk = lin & 63;
            Bs[kk][n] = B[(size_t)(n0 + n) * 256 + (k0 + kk)];
        }
        __syncthreads();
#pragma unroll 8
        for (int kk = 0; kk < 64; kk++) {
            float a[4], b[4];
#pragma unroll
            for (int i = 0; i < 4; i++) a[i] = As[ty * 4 + i][kk];
#pragma unroll
            for (int j = 0; j < 4; j++) b[j] = Bs[kk][tx * 4 + j];
#pragma unroll
            for (int i = 0; i < 4; i++)
#pragma unroll
                for (int j = 0; j < 4; j++) acc[i][j] += a[i] * b[j];
        }
        __syncthreads();
    }

#pragma unroll
    for (int i = 0; i < 4; i++) {
        int m = m0 + ty * 4 + i;
#pragma unroll
        for (int j = 0; j < 4; j++) {
            int n = n0 + tx * 4 + j;
            C[(size_t)m * 768 + n] = acc[i][j] + bias[n];
        }
    }
}

// ---------------- WMMA tf32 streaming attention ------------------------------
#define LDQ 268
#define LDP 76
__global__ __launch_bounds__(256) void attn_kernel(const float* __restrict__ Q,
                                                   const float* __restrict__ K,
                                                   const float* __restrict__ V,
                                                   float* __restrict__ O) {
    extern __shared__ float sm[];
    float* Qs = sm;
    float* Ks = Qs + 64 * LDQ;
    float* Vs = Ks + 64 * LDQ;
    float* Ps = Vs + 64 * LDQ;
    float* Ls = Ps + 64 * LDP;

    int h = blockIdx.y;
    int q0 = blockIdx.x * 64;
    int tid = threadIdx.x;
    int warp = tid >> 5;
    int wm = warp & 3;
    int wn = warp >> 2;

    const float* Qg = Q + ((size_t)h * S + q0) * H;
    const float* Kg = K + (size_t)h * S * H;
    const float* Vg = V + (size_t)h * S * H;

    for (int i = tid; i < 64 * 64; i += 256) {
        int q = i >> 6, d4 = i & 63;
        ((float4*)(Qs + q * LDQ))[d4] = ((const float4*)(Qg + (size_t)q * H))[d4];
    }

    wmma::fragment<wmma::accumulator, 16, 16, 8, float> o_frag[8];
#pragma unroll
    for (int f = 0; f < 8; f++) wmma::fill_fragment(o_frag[f], 0.0f);

    int lrow = tid >> 2;
    int lcol0 = (tid & 3) * 16;
    float l_part = 0.f;
    const float inv_scale = 0.0625f;

    for (int kt = 0; kt < S / 64; kt++) {
        __syncthreads();
        for (int i = tid; i < 64 * 64; i += 256) {
            int r = i >> 6, d4 = i & 63;
            ((float4*)(Ks + r * LDQ))[d4] =
                ((const float4*)(Kg + (size_t)(kt * 64 + r) * H))[d4];
            ((float4*)(Vs + r * LDQ))[d4] =
                ((const float4*)(Vg + (size_t)(kt * 64 + r) * H))[d4];
        }
        __syncthreads();

        {
            wmma::fragment<wmma::matrix_a, 16, 16, 8, wmma::precision::tf32,
                           wmma::row_major> af;
            wmma::fragment<wmma::matrix_b, 16, 16, 8, wmma::precision::tf32,
                           wmma::col_major> bf;
            wmma::fragment<wmma::accumulator, 16, 16, 8, float> c[2];
            wmma::fill_fragment(c[0], 0.0f);
            wmma::fill_fragment(c[1], 0.0f);
#pragma unroll 4
            for (int k = 0; k < 32; k++) {
                wmma::load_matrix_sync(af, Qs + (wm * 16) * LDQ + k * 8, LDQ);
#pragma unroll
                for (int e = 0; e < af.num_elements; e++)
                    af.x[e] = wmma::__float_to_tf32(af.x[e]);
#pragma unroll
                for (int nf = 0; nf < 2; nf++) {
                    wmma::load_matrix_sync(
                        bf, Ks + (wn * 32 + nf * 16) * LDQ + k * 8, LDQ);
#pragma unroll
                    for (int e = 0; e < bf.num_elements; e++)
                        bf.x[e] = wmma::__float_to_tf32(bf.x[e]);
                    wmma::mma_sync(c[nf], af, bf, c[nf]);
                }
            }
#pragma unroll
            for (int nf = 0; nf < 2; nf++)
                wmma::store_matrix_sync(
                    Ps + (wm * 16) * LDP + wn * 32 + nf * 16, c[nf], LDP,
                    wmma::mem_row_major);
        }
        __syncthreads();

        {
            float* pr = Ps + lrow * LDP + lcol0;
            float ssum = 0.f;
#pragma unroll
            for (int j = 0; j < 16; j++) {
                float e = __expf(pr[j] * inv_scale);
                pr[j] = e;
                ssum += e;
            }
            l_part += ssum;
        }
        __syncthreads();

        {
            wmma::fragment<wmma::matrix_a, 16, 16, 8, wmma::precision::tf32,
                           wmma::row_major> pa;
            wmma::fragment<wmma::matrix_b, 16, 16, 8, wmma::precision::tf32,
                           wmma::row_major> vb;
#pragma unroll
            for (int k = 0; k < 8; k++) {
                wmma::load_matrix_sync(pa, Ps + (wm * 16) * LDP + k * 8, LDP);
#pragma unroll
                for (int e = 0; e < pa.num_elements; e++)
                    pa.x[e] = wmma::__float_to_tf32(pa.x[e]);
#pragma unroll
                for (int nf = 0; nf < 8; nf++) {
                    wmma::load_matrix_sync(
                        vb, Vs + (k * 8) * LDQ + wn * 128 + nf * 16, LDQ);
#pragma unroll
                    for (int e = 0; e < vb.num_elements; e++)
                        vb.x[e] = wmma::__float_to_tf32(vb.x[e]);
                    wmma::mma_sync(o_frag[nf], pa, vb, o_frag[nf]);
                }
            }
        }
    }

    l_part += __shfl_xor_sync(0xffffffffu, l_part, 1);
    l_part += __shfl_xor_sync(0xffffffffu, l_part, 2);
    if ((tid & 3) == 0) Ls[lrow] = l_part;

#pragma unroll
    for (int nf = 0; nf < 8; nf++)
        wmma::store_matrix_sync(Qs + (wm * 16) * LDQ + wn * 128 + nf * 16,
                                o_frag[nf], LDQ, wmma::mem_row_major);
    __syncthreads();

    float* Og = O + ((size_t)h * S + q0) * H;
    for (int i = tid; i < 64 * 64; i += 256) {
        int q = i >> 6, d4 = i & 63;
        float inv_l = __frcp_rn(Ls[q]);
        float4 v = ((float4*)(Qs + q * LDQ))[d4];
        v.x *= inv_l; v.y *= inv_l; v.z *= inv_l; v.w *= inv_l;
        ((float4*)(Og + (size_t)q * H))[d4] = v;
    }
}

// ---------------- LayerNorm (one warp per row) ----------------
__global__ __launch_bounds__(256) void ln_kernel(const float* __restrict__ yin,
                                                 const float* __restrict__ g,
                                                 const float* __restrict__ b,
                                                 float* __restrict__ yout) {
    int row = blockIdx.x * 8 + (threadIdx.x >> 5);
    int lane = threadIdx.x & 31;
    const float* yr = yin + (size_t)row * H;
    float v[8], s = 0.f, sq = 0.f;
#pragma unroll
    for (int i = 0; i < 8; i++) {
        v[i] = yr[lane + i * 32];
        s += v[i];
        sq += v[i] * v[i];
    }
#pragma unroll
    for (int m = 16; m >= 1; m >>= 1) {
        s += __shfl_xor_sync(0xffffffffu, s, m);
        sq += __shfl_xor_sync(0xffffffffu, sq, m);
    }
    float mu = s * (1.f / H);
    float var = sq * (1.f / H) - mu * mu;
    float rstd = rsqrtf(var + EPS);
    float* yo = yout + (size_t)row * H;
#pragma unroll
    for (int i = 0; i < 8; i++) {
        int c = lane + i * 32;
        yo[c] = (v[i] - mu) * rstd * g[c] + b[c];
    }
}

// ---------------- GRU recurrence: 8-CTA cluster, 16B-packet st.async ---------
// R14: 8 warps/CTA (256 threads). Warp w owns 4 dims (12 W_hh rows in regs,
// 48 FFMA2/thread). Two-level role-fold butterfly (18 shfls) lands row totals
// for dim dd=lane&3 on every lane; lanes 0..3 run the gates. Lanes 0..7 each
// send ONE st.async.v4.b32 (16B: 4 dims) to CTA==lane -> 64 messages/receiver
// instead of 128 (halves the DSMEM small-message port serialization).
// Sync skeleton identical to R11: single mbar per parity, lane0 waiter,
// off-path re-arm by tid0.
#define RB 8
#define RT 256

__device__ __forceinline__ unsigned int smem_u32(const void* p) {
    unsigned int a;
    asm("{ .reg .u64 t; cvta.to.shared.u64 t, %1; cvt.u32.u64 %0, t; }"
        : "=r"(a) : "l"(p));
    return a;
}

__device__ __forceinline__ void cluster_arrive_wait() {
    asm volatile("barrier.cluster.arrive.aligned;" ::: "memory");
    asm volatile("barrier.cluster.wait.aligned;" ::: "memory");
}

__device__ __forceinline__ void mbar_wait_parity(unsigned int mb,
                                                 unsigned int parity) {
    asm volatile(
        "{\n\t"
        ".reg .pred P;\n\t"
        "WL%=:\n\t"
        "mbarrier.try_wait.parity.acquire.cta.shared::cta.b64 P, [%0], %1, 0x989680;\n\t"
        "@!P bra WL%=;\n\t"
        "}"
        :: "r"(mb), "r"(parity) : "memory");
}

__global__ void __cluster_dims__(RB, 1, 1) __launch_bounds__(RT, 1)
rnn_kernel(const float* __restrict__ gi,
           const float* __restrict__ Whh,
           const float* __restrict__ bhh,
           float* __restrict__ out,
           int out_size) {
    __shared__ __align__(16) float hbuf[2][H];
    __shared__ __align__(8) unsigned long long mbar[2];

    int blk = blockIdx.x;
    int tid = threadIdx.x;
    int w = tid >> 5;                 // warp 0..7
    int lane = tid & 31;

    // weights: rows (g, dd) -> global row g*256 + blk*32 + w*4 + dd (12 rows),
    // cols lane*8..lane*8+7 packed f32x2: 12 x 4 ull = 48 ull
    unsigned long long w2[12][4];
#pragma unroll
    for (int g = 0; g < 3; g++) {
#pragma unroll
        for (int dd = 0; dd < 4; dd++) {
            int rowg = g * 256 + blk * 32 + w * 4 + dd;
            const unsigned long long* src =
                (const unsigned long long*)(Whh + (size_t)rowg * H + lane * 8);
#pragma unroll
            for (int i = 0; i < 4; i++) w2[g * 4 + dd][i] = src[i];
        }
    }

    for (int i = tid; i < 2 * H; i += RT) ((float*)hbuf)[i] = 0.f;

    unsigned int mb0 = smem_u32(&mbar[0]);
    unsigned int mb1 = smem_u32(&mbar[1]);
    if (tid == 0) {
        asm volatile("mbarrier.init.shared.b64 [%0], %1;"
                     :: "r"(mb0), "r"(1) : "memory");
        asm volatile("mbarrier.init.shared.b64 [%0], %1;"
                     :: "r"(mb1), "r"(1) : "memory");
        // pre-arm both parities: 8 CTAs * 8 warps * 16B = 1024B
        asm volatile("mbarrier.arrive.expect_tx.shared.b64 _, [%0], %1;"
                     :: "r"(mb0), "r"(1024) : "memory");
        asm volatile("mbarrier.arrive.expect_tx.shared.b64 _, [%0], %1;"
                     :: "r"(mb1), "r"(1024) : "memory");
    }

    // owner lanes 0..3 of each warp own dim d = w*4 + lane
    int d = w * 4 + lane;             // meaningful for lane < 4
    int j = blk * 32 + d;
    int jc = j & 255;
    bool owner = (lane < 4);
    float ir = 0.f, iz = 0.f, inn = 0.f, bh_r = 0.f, bh_z = 0.f, bh_n = 0.f;
    if (owner) {
        ir = gi[j];
        iz = gi[256 + j];
        inn = gi[512 + j];
        bh_r = bhh[j];
        bh_z = bhh[256 + j];
        bh_n = bhh[512 + j];
    }
    unsigned int hb0 = smem_u32(&hbuf[0][lane * 8]);
    unsigned int hb1 = smem_u32(&hbuf[1][lane * 8]);

    // remote addresses: warp slot (4 dims = 16B) in each target CTA
    unsigned int wl0 = smem_u32(&hbuf[0][blk * 32 + w * 4]);
    unsigned int wl1 = smem_u32(&hbuf[1][blk * 32 + w * 4]);
    int rr = lane & 7;
    unsigned int pdst0, pdst1, pmb0, pmb1;
    asm("mapa.shared::cluster.u32 %0, %1, %2;" : "=r"(pdst0) : "r"(wl0), "r"(rr));
    asm("mapa.shared::cluster.u32 %0, %1, %2;" : "=r"(pdst1) : "r"(wl1), "r"(rr));
    asm("mapa.shared::cluster.u32 %0, %1, %2;" : "=r"(pmb0) : "r"(mb0), "r"(rr));
    asm("mapa.shared::cluster.u32 %0, %1, %2;" : "=r"(pmb1) : "r"(mb1), "r"(rr));

    __syncthreads();
    cluster_arrive_wait();

    for (int t = 0; t < S; t++) {
        int p = t & 1;

        // ---- dot: 12 rows x 8 cols per thread (f32x2) ----
        unsigned int haddr = p ? hb1 : hb0;
        unsigned long long h2[4];
        asm volatile("ld.shared.v2.b64 {%0, %1}, [%4];\n\t"
                     "ld.shared.v2.b64 {%2, %3}, [%4 + 16];"
                     : "=l"(h2[0]), "=l"(h2[1]), "=l"(h2[2]), "=l"(h2[3])
                     : "r"(haddr));
        float a[12];
#pragma unroll
        for (int r = 0; r < 12; r++) {
            unsigned long long acc2 = 0ull;
#pragma unroll
            for (int i = 0; i < 4; i++) {
                asm("fma.rn.f32x2 %0, %1, %2, %0;"
                    : "+l"(acc2) : "l"(w2[r][i]), "l"(h2[i]));
            }
            float lo, hi;
            asm("mov.b64 {%0, %1}, %2;" : "=f"(lo), "=f"(hi) : "l"(acc2));
            a[r] = lo + hi;
        }

        // ---- two-level role-fold butterfly: 12 -> 6 -> 3 arrays ----
        int l0 = lane & 1;
        int l1 = (lane >> 1) & 1;
        float b6[6];
#pragma unroll
        for (int g = 0; g < 3; g++) {
#pragma unroll
            for (int d1 = 0; d1 < 2; d1++) {
                float x = a[g * 4 + (d1 << 1) + 0];
                float y = a[g * 4 + (d1 << 1) + 1];
                float keep = l0 ? y : x;
                float send = l0 ? x : y;
                b6[g * 2 + d1] = keep + __shfl_xor_sync(0xffffffffu, send, 1);
            }
        }
        float z3[3];
#pragma unroll
        for (int g = 0; g < 3; g++) {
            float x = b6[g * 2 + 0];
            float y = b6[g * 2 + 1];
            float keep = l1 ? y : x;
            float send = l1 ? x : y;
            z3[g] = keep + __shfl_xor_sync(0xffffffffu, send, 2);
        }
#pragma unroll
        for (int m = 4; m <= 16; m <<= 1) {
#pragma unroll
            for (int g = 0; g < 3; g++)
                z3[g] += __shfl_xor_sync(0xffffffffu, z3[g], m);
        }
        // lane's dd = lane&3: z3[g] = total for row g*256 + blk*32 + w*4 + dd

        // ---- gate math (all lanes SIMT; lanes 0..3 meaningful) ----
        float ghr = z3[0] + bh_r;
        float ghz = z3[1] + bh_z;
        float ghn = z3[2] + bh_n;
        float hold = hbuf[p][jc];
        float r = 1.f / (1.f + __expf(-(ir + ghr)));
        float z = 1.f / (1.f + __expf(-(iz + ghz)));
        float narg = inn + r * ghn;
        float n = 1.f - 2.f / (1.f + __expf(2.f * narg));
        float hnew = (1.f - z) * n + z * hold;

        // broadcast the warp's 4 dims
        float b0 = __shfl_sync(0xffffffffu, hnew, 0);
        float b1 = __shfl_sync(0xffffffffu, hnew, 1);
        float b2 = __shfl_sync(0xffffffffu, hnew, 2);
        float b3 = __shfl_sync(0xffffffffu, hnew, 3);

        // ---- st.async exchange: lanes 0..7, one 16B packet each ----
        if (lane < 8) {
            unsigned int pd = p ? pdst0 : pdst1;   // write hbuf[p^1]
            unsigned int pm = p ? pmb1 : pmb0;     // count on mbar[p]
            asm volatile(
                "st.async.shared::cluster.mbarrier::complete_tx::bytes.v4.b32 "
                "[%0], {%1, %2, %3, %4}, [%5];"
                :: "r"(pd), "f"(b0), "f"(b1), "f"(b2), "f"(b3), "r"(pm)
                : "memory");
        }

        // prefetch next token's gi (hidden by the wait)
        if (owner) {
            int tn = (t + 1 < S) ? (t + 1) : t;
            ir = gi[(size_t)tn * G3 + j];
            iz = gi[(size_t)tn * G3 + 256 + j];
            inn = gi[(size_t)tn * G3 + 512 + j];
        }

        // ---- elected waiter per warp; tid0 re-arms for phase t+2 ----
        unsigned int mbp = p ? mb1 : mb0;
        if (lane == 0) {
            mbar_wait_parity(mbp, (unsigned int)((t >> 1) & 1));
            if (tid == 0) {
                asm volatile("mbarrier.arrive.expect_tx.shared.b64 _, [%0], %1;"
                             :: "r"(mbp), "r"(1024) : "memory");
            }
        }
        __syncwarp();
    }

    if (blk == 0) {
        for (int i = tid; i < out_size; i += RT)
            out[i] = hbuf[0][i & 255];
    }
}

// ---------------- host launcher ----------------
extern "C" void kernel_launch(void* const* d_in, const int* in_sizes, int n_in,
                              void* d_out, int out_size) {
    const int* tokens = (const int*)d_in[0];
    const float* emb = (const float*)d_in[1];
    const float* Wq = (const float*)d_in[2];
    const float* bq = (const float*)d_in[3];
    const float* Wk = (const float*)d_in[4];
    const float* bk = (const float*)d_in[5];
    const float* Wv = (const float*)d_in[6];
    const float* bv = (const float*)d_in[7];
    const float* Wo = (const float*)d_in[8];
    const float* bo = (const float*)d_in[9];
    const float* ln_g = (const float*)d_in[10];
    const float* ln_b = (const float*)d_in[11];
    const float* W_ih = (const float*)d_in[12];
    const float* W_hh = (const float*)d_in[13];
    const float* b_ih = (const float*)d_in[14];
    const float* b_hh = (const float*)d_in[15];
    float* out = (float*)d_out;

    float* px; cudaGetSymbolAddress((void**)&px, g_x);
    float* pq; cudaGetSymbolAddress((void**)&pq, g_q);
    float* pk; cudaGetSymbolAddress((void**)&pk, g_k);
    float* pv; cudaGetSymbolAddress((void**)&pv, g_v);
    float* po; cudaGetSymbolAddress((void**)&po, g_o);
    float* pypre; cudaGetSymbolAddress((void**)&pypre, g_ypre);
    float* py; cudaGetSymbolAddress((void**)&py, g_y);
    float* pgi; cudaGetSymbolAddress((void**)&pgi, g_gi);

    size_t attn_smem = (size_t)(3 * 64 * LDQ + 64 * LDP + 64) * sizeof(float);
    cudaFuncSetAttribute(attn_kernel, cudaFuncAttributeMaxDynamicSharedMemorySize,
                         (int)attn_smem);

    embed_kernel<<<S, 64>>>(tokens, emb);

    dim3 gqkv(4, 64, 3 * NH);
    gemm_qkv<<<gqkv, 256>>>(px, Wq, bq, Wk, bk, Wv, bv, pq, pk, pv);

    dim3 gatt(S / 64, NH);
    attn_kernel<<<gatt, 256, attn_smem>>>(pq, pk, pv, po);

    dim3 gop(4, 64, 1);
    gemm_op<<<gop, 256>>>(po, Wo, bo, px, pypre);

    ln_kernel<<<S / 8, 256>>>(pypre, ln_g, ln_b, py);

    dim3 ggi(12, 64, 1);
    gemm_gi<<<ggi, 256>>>(py, W_ih, b_ih, pgi);

    rnn_kernel<<<RB, RT>>>(pgi, W_hh, b_hh, out, out_size);
}